// round 1
// baseline (speedup 1.0000x reference)
#include <cuda_runtime.h>
#include <math.h>

// Problem constants (fixed by setup_inputs)
#define NB   64
#define LL   1024
#define DM   512
#define ROWS (NB*LL)          // 65536

// ---------------- scratch (static device globals; no allocation) ----------
__device__ float g_Q   [(size_t)ROWS*DM];
__device__ float g_Kf  [(size_t)ROWS*DM];
__device__ float g_Vf  [(size_t)ROWS*DM];
__device__ float g_KV  [(size_t)NB*DM*DM];
__device__ float g_Ksum[NB*DM];
__device__ float g_Z   [ROWS];
__device__ float g_msg [(size_t)ROWS*DM];
__device__ float g_msg2[(size_t)ROWS*DM];
__device__ float g_t   [(size_t)ROWS*2*DM];
__device__ float g_h2  [(size_t)ROWS*DM];

enum { EPI_NONE=0, EPI_ELU1=1, EPI_MASK=2 };

// =====================================================================
// NT GEMM:  C[M,N] = A[M,K] @ B[N,K]^T   (both row-major, K contiguous)
// 128x128 tile, BK=16, 256 threads, 8x8 per thread (4x4 quad split).
// =====================================================================
template<int EPI>
__global__ void __launch_bounds__(256,2)
gemm_nt(const float* __restrict__ A, const float* __restrict__ B,
        float* __restrict__ C, int M, int N, int K,
        const float* __restrict__ rs)
{
    __shared__ float As[16][132];
    __shared__ float Bs[16][132];
    const int bm = blockIdx.y * 128;
    const int bn = blockIdx.x * 128;
    const int tid = threadIdx.x;
    const int tx = tid & 15;
    const int ty = tid >> 4;

    float acc[8][8];
#pragma unroll
    for (int i=0;i<8;i++)
#pragma unroll
        for (int j=0;j<8;j++) acc[i][j]=0.f;

    for (int k0 = 0; k0 < K; k0 += 16) {
#pragma unroll
        for (int it=0; it<2; it++) {
            int idx = tid + it*256;
            int r  = idx >> 2;
            int kq = idx & 3;
            float4 va = *(const float4*)(A + (size_t)(bm+r)*K + k0 + kq*4);
            As[kq*4+0][r]=va.x; As[kq*4+1][r]=va.y;
            As[kq*4+2][r]=va.z; As[kq*4+3][r]=va.w;
            float4 vb = *(const float4*)(B + (size_t)(bn+r)*K + k0 + kq*4);
            Bs[kq*4+0][r]=vb.x; Bs[kq*4+1][r]=vb.y;
            Bs[kq*4+2][r]=vb.z; Bs[kq*4+3][r]=vb.w;
        }
        __syncthreads();
#pragma unroll
        for (int k=0;k<16;k++) {
            float4 a0 = *(const float4*)&As[k][ty*4];
            float4 a1 = *(const float4*)&As[k][64+ty*4];
            float4 b0 = *(const float4*)&Bs[k][tx*4];
            float4 b1 = *(const float4*)&Bs[k][64+tx*4];
            float a[8] = {a0.x,a0.y,a0.z,a0.w,a1.x,a1.y,a1.z,a1.w};
            float b[8] = {b0.x,b0.y,b0.z,b0.w,b1.x,b1.y,b1.z,b1.w};
#pragma unroll
            for (int i=0;i<8;i++)
#pragma unroll
                for (int j=0;j<8;j++) acc[i][j] = fmaf(a[i],b[j],acc[i][j]);
        }
        __syncthreads();
    }

#pragma unroll
    for (int i=0;i<8;i++) {
        int r = bm + ((i<4) ? ty*4+i : 64+ty*4+(i-4));
        float sc = 1.f;
        if (EPI==EPI_ELU1 || EPI==EPI_MASK) sc = rs[r];
        float o[8];
#pragma unroll
        for (int j=0;j<8;j++) {
            float v = acc[i][j];
            if (EPI==EPI_ELU1)      v = (v > 0.f ? v + 1.f : expf(v)) * sc;
            else if (EPI==EPI_MASK) v = v * sc;
            o[j]=v;
        }
        float4 o0 = {o[0],o[1],o[2],o[3]};
        float4 o1 = {o[4],o[5],o[6],o[7]};
        *(float4*)(C + (size_t)r*N + bn + tx*4)      = o0;
        *(float4*)(C + (size_t)r*N + bn + 64 + tx*4) = o1;
    }
}

// =====================================================================
// Concat NT GEMM with ReLU:  C = relu( [A1 | A2] @ B^T )
// A1,A2: [65536,512]; B(W1): [1024,1024]; C: [65536,1024]; K=1024
// =====================================================================
__global__ void __launch_bounds__(256,2)
gemm_cat_relu(const float* __restrict__ A1, const float* __restrict__ A2,
              const float* __restrict__ B, float* __restrict__ C)
{
    const int N = 2*DM, K = 2*DM;
    __shared__ float As[16][132];
    __shared__ float Bs[16][132];
    const int bm = blockIdx.y * 128;
    const int bn = blockIdx.x * 128;
    const int tid = threadIdx.x;
    const int tx = tid & 15;
    const int ty = tid >> 4;

    float acc[8][8];
#pragma unroll
    for (int i=0;i<8;i++)
#pragma unroll
        for (int j=0;j<8;j++) acc[i][j]=0.f;

    for (int k0 = 0; k0 < K; k0 += 16) {
#pragma unroll
        for (int it=0; it<2; it++) {
            int idx = tid + it*256;
            int r  = idx >> 2;
            int kq = idx & 3;
            int kk = k0 + kq*4;
            float4 va;
            if (kk < DM) va = *(const float4*)(A1 + (size_t)(bm+r)*DM + kk);
            else         va = *(const float4*)(A2 + (size_t)(bm+r)*DM + (kk-DM));
            As[kq*4+0][r]=va.x; As[kq*4+1][r]=va.y;
            As[kq*4+2][r]=va.z; As[kq*4+3][r]=va.w;
            float4 vb = *(const float4*)(B + (size_t)(bn+r)*K + kk);
            Bs[kq*4+0][r]=vb.x; Bs[kq*4+1][r]=vb.y;
            Bs[kq*4+2][r]=vb.z; Bs[kq*4+3][r]=vb.w;
        }
        __syncthreads();
#pragma unroll
        for (int k=0;k<16;k++) {
            float4 a0 = *(const float4*)&As[k][ty*4];
            float4 a1 = *(const float4*)&As[k][64+ty*4];
            float4 b0 = *(const float4*)&Bs[k][tx*4];
            float4 b1 = *(const float4*)&Bs[k][64+tx*4];
            float a[8] = {a0.x,a0.y,a0.z,a0.w,a1.x,a1.y,a1.z,a1.w};
            float b[8] = {b0.x,b0.y,b0.z,b0.w,b1.x,b1.y,b1.z,b1.w};
#pragma unroll
            for (int i=0;i<8;i++)
#pragma unroll
                for (int j=0;j<8;j++) acc[i][j] = fmaf(a[i],b[j],acc[i][j]);
        }
        __syncthreads();
    }

#pragma unroll
    for (int i=0;i<8;i++) {
        int r = bm + ((i<4) ? ty*4+i : 64+ty*4+(i-4));
        float o[8];
#pragma unroll
        for (int j=0;j<8;j++) o[j] = fmaxf(acc[i][j], 0.f);
        float4 o0 = {o[0],o[1],o[2],o[3]};
        float4 o1 = {o[4],o[5],o[6],o[7]};
        *(float4*)(C + (size_t)r*N + bn + tx*4)      = o0;
        *(float4*)(C + (size_t)r*N + bn + 64 + tx*4) = o1;
    }
}

// =====================================================================
// Batched TN GEMM:  KV[n] = K[n]^T @ V[n]
// per batch: A,B = [1024,512]; C = [512,512]; sum over s (K-dim=1024)
// =====================================================================
__global__ void __launch_bounds__(256,2)
gemm_tn_batch(const float* __restrict__ A, const float* __restrict__ B,
              float* __restrict__ C)
{
    __shared__ float As[16][128];
    __shared__ float Bs[16][128];
    const int n  = blockIdx.z;
    const float* Ab = A + (size_t)n*LL*DM;
    const float* Bb = B + (size_t)n*LL*DM;
    float*       Cb = C + (size_t)n*DM*DM;
    const int bm = blockIdx.y * 128;
    const int bn = blockIdx.x * 128;
    const int tid = threadIdx.x;
    const int tx = tid & 15;
    const int ty = tid >> 4;

    float acc[8][8];
#pragma unroll
    for (int i=0;i<8;i++)
#pragma unroll
        for (int j=0;j<8;j++) acc[i][j]=0.f;

    for (int k0 = 0; k0 < LL; k0 += 16) {
#pragma unroll
        for (int it=0; it<2; it++) {
            int idx = tid + it*256;
            int kr = idx >> 5;
            int c4 = idx & 31;
            *(float4*)&As[kr][c4*4] =
                *(const float4*)(Ab + (size_t)(k0+kr)*DM + bm + c4*4);
            *(float4*)&Bs[kr][c4*4] =
                *(const float4*)(Bb + (size_t)(k0+kr)*DM + bn + c4*4);
        }
        __syncthreads();
#pragma unroll
        for (int k=0;k<16;k++) {
            float4 a0 = *(const float4*)&As[k][ty*4];
            float4 a1 = *(const float4*)&As[k][64+ty*4];
            float4 b0 = *(const float4*)&Bs[k][tx*4];
            float4 b1 = *(const float4*)&Bs[k][64+tx*4];
            float a[8] = {a0.x,a0.y,a0.z,a0.w,a1.x,a1.y,a1.z,a1.w};
            float b[8] = {b0.x,b0.y,b0.z,b0.w,b1.x,b1.y,b1.z,b1.w};
#pragma unroll
            for (int i=0;i<8;i++)
#pragma unroll
                for (int j=0;j<8;j++) acc[i][j] = fmaf(a[i],b[j],acc[i][j]);
        }
        __syncthreads();
    }

#pragma unroll
    for (int i=0;i<8;i++) {
        int r = bm + ((i<4) ? ty*4+i : 64+ty*4+(i-4));
        float4 o0 = {acc[i][0],acc[i][1],acc[i][2],acc[i][3]};
        float4 o1 = {acc[i][4],acc[i][5],acc[i][6],acc[i][7]};
        *(float4*)(Cb + (size_t)r*DM + bn + tx*4)      = o0;
        *(float4*)(Cb + (size_t)r*DM + bn + 64 + tx*4) = o1;
    }
}

// =====================================================================
// Batched NN GEMM with Z-scale:  msg[n] = (Q[n] @ KV[n]) * Z[row]
// per batch: A = [1024,512], B = [512,512], C = [1024,512]
// =====================================================================
__global__ void __launch_bounds__(256,2)
gemm_nn_batch(const float* __restrict__ A, const float* __restrict__ B,
              float* __restrict__ C, const float* __restrict__ Z)
{
    __shared__ float As[16][132];
    __shared__ float Bs[16][128];
    const int n  = blockIdx.z;
    const float* Ab = A + (size_t)n*LL*DM;
    const float* Bb = B + (size_t)n*DM*DM;
    float*       Cb = C + (size_t)n*LL*DM;
    const int bm = blockIdx.y * 128;   // over L
    const int bn = blockIdx.x * 128;   // over dv
    const int tid = threadIdx.x;
    const int tx = tid & 15;
    const int ty = tid >> 4;

    float acc[8][8];
#pragma unroll
    for (int i=0;i<8;i++)
#pragma unroll
        for (int j=0;j<8;j++) acc[i][j]=0.f;

    for (int k0 = 0; k0 < DM; k0 += 16) {
#pragma unroll
        for (int it=0; it<2; it++) {
            int idx = tid + it*256;
            // A: transpose into As[k][m]
            int r  = idx >> 2;
            int kq = idx & 3;
            float4 va = *(const float4*)(Ab + (size_t)(bm+r)*DM + k0 + kq*4);
            As[kq*4+0][r]=va.x; As[kq*4+1][r]=va.y;
            As[kq*4+2][r]=va.z; As[kq*4+3][r]=va.w;
            // B: natural rows
            int kr = idx >> 5;
            int c4 = idx & 31;
            *(float4*)&Bs[kr][c4*4] =
                *(const float4*)(Bb + (size_t)(k0+kr)*DM + bn + c4*4);
        }
        __syncthreads();
#pragma unroll
        for (int k=0;k<16;k++) {
            float4 a0 = *(const float4*)&As[k][ty*4];
            float4 a1 = *(const float4*)&As[k][64+ty*4];
            float4 b0 = *(const float4*)&Bs[k][tx*4];
            float4 b1 = *(const float4*)&Bs[k][64+tx*4];
            float a[8] = {a0.x,a0.y,a0.z,a0.w,a1.x,a1.y,a1.z,a1.w};
            float b[8] = {b0.x,b0.y,b0.z,b0.w,b1.x,b1.y,b1.z,b1.w};
#pragma unroll
            for (int i=0;i<8;i++)
#pragma unroll
                for (int j=0;j<8;j++) acc[i][j] = fmaf(a[i],b[j],acc[i][j]);
        }
        __syncthreads();
    }

#pragma unroll
    for (int i=0;i<8;i++) {
        int rl = bm + ((i<4) ? ty*4+i : 64+ty*4+(i-4));
        float z = Z[n*LL + rl];
        float4 o0 = {acc[i][0]*z,acc[i][1]*z,acc[i][2]*z,acc[i][3]*z};
        float4 o1 = {acc[i][4]*z,acc[i][5]*z,acc[i][6]*z,acc[i][7]*z};
        *(float4*)(Cb + (size_t)rl*DM + bn + tx*4)      = o0;
        *(float4*)(Cb + (size_t)rl*DM + bn + 64 + tx*4) = o1;
    }
}

// ---------------- Ksum: Ksum[n][d] = sum_s K[n][s][d] ---------------------
__global__ void ksum_kernel(const float* __restrict__ Kf, float* __restrict__ Ks)
{
    int idx = blockIdx.x*blockDim.x + threadIdx.x;   // 0..NB*DM-1
    int n = idx >> 9;
    int d = idx & (DM-1);
    const float* p = Kf + (size_t)n*LL*DM + d;
    float s = 0.f;
    for (int ss = 0; ss < LL; ss++) s += p[(size_t)ss*DM];
    Ks[idx] = s;
}

// ---------------- Z: Z[r] = 1/(dot(Q[r], Ksum[n]) + 1e-6) -----------------
__global__ void z_kernel(const float* __restrict__ Q,
                         const float* __restrict__ Ks,
                         float* __restrict__ Z)
{
    int gw   = (blockIdx.x*blockDim.x + threadIdx.x) >> 5;   // row
    int lane = threadIdx.x & 31;
    if (gw >= ROWS) return;
    int n = gw >> 10;
    const float* q = Q  + (size_t)gw*DM;
    const float* k = Ks + n*DM;
    float s = 0.f;
#pragma unroll
    for (int i = 0; i < DM/32; i++) s = fmaf(q[lane + i*32], k[lane + i*32], s);
#pragma unroll
    for (int off = 16; off; off >>= 1) s += __shfl_xor_sync(0xffffffffu, s, off);
    if (lane == 0) Z[gw] = 1.f / (s + 1e-6f);
}

// ---------------- LayerNorm over rows of 512 (g,b affine) -----------------
__global__ void ln_kernel(const float* __restrict__ in,
                          const float* __restrict__ g, const float* __restrict__ b,
                          float* __restrict__ out)
{
    int row = blockIdx.x;
    int tid = threadIdx.x;                 // 128 threads, 4 elems each
    float4 v = *(const float4*)(in + (size_t)row*DM + tid*4);
    __shared__ float red[128];
    red[tid] = v.x + v.y + v.z + v.w;
    __syncthreads();
    for (int off = 64; off; off >>= 1) {
        if (tid < off) red[tid] += red[tid+off];
        __syncthreads();
    }
    float mu = red[0] * (1.f/DM);
    __syncthreads();
    float dx = v.x-mu, dy = v.y-mu, dz = v.z-mu, dw = v.w-mu;
    red[tid] = dx*dx + dy*dy + dz*dz + dw*dw;
    __syncthreads();
    for (int off = 64; off; off >>= 1) {
        if (tid < off) red[tid] += red[tid+off];
        __syncthreads();
    }
    float rstd = rsqrtf(red[0] * (1.f/DM) + 1e-5f);
    float4 gv = *(const float4*)(g + tid*4);
    float4 bv = *(const float4*)(b + tid*4);
    float4 o;
    o.x = dx*rstd*gv.x + bv.x;
    o.y = dy*rstd*gv.y + bv.y;
    o.z = dz*rstd*gv.z + bv.z;
    o.w = dw*rstd*gv.w + bv.w;
    *(float4*)(out + (size_t)row*DM + tid*4) = o;
}

// ---------------- LayerNorm + residual: out = x + LN(h) -------------------
__global__ void ln_res_kernel(const float* __restrict__ in,
                              const float* __restrict__ x,
                              const float* __restrict__ g, const float* __restrict__ b,
                              float* __restrict__ out)
{
    int row = blockIdx.x;
    int tid = threadIdx.x;
    float4 v = *(const float4*)(in + (size_t)row*DM + tid*4);
    __shared__ float red[128];
    red[tid] = v.x + v.y + v.z + v.w;
    __syncthreads();
    for (int off = 64; off; off >>= 1) {
        if (tid < off) red[tid] += red[tid+off];
        __syncthreads();
    }
    float mu = red[0] * (1.f/DM);
    __syncthreads();
    float dx = v.x-mu, dy = v.y-mu, dz = v.z-mu, dw = v.w-mu;
    red[tid] = dx*dx + dy*dy + dz*dz + dw*dw;
    __syncthreads();
    for (int off = 64; off; off >>= 1) {
        if (tid < off) red[tid] += red[tid+off];
        __syncthreads();
    }
    float rstd = rsqrtf(red[0] * (1.f/DM) + 1e-5f);
    float4 gv = *(const float4*)(g + tid*4);
    float4 bv = *(const float4*)(b + tid*4);
    float4 xv = *(const float4*)(x + (size_t)row*DM + tid*4);
    float4 o;
    o.x = xv.x + dx*rstd*gv.x + bv.x;
    o.y = xv.y + dy*rstd*gv.y + bv.y;
    o.z = xv.z + dz*rstd*gv.z + bv.z;
    o.w = xv.w + dw*rstd*gv.w + bv.w;
    *(float4*)(out + (size_t)row*DM + tid*4) = o;
}

// =====================================================================
extern "C" void kernel_launch(void* const* d_in, const int* in_sizes, int n_in,
                              void* d_out, int out_size)
{
    const float* x   = (const float*)d_in[0];
    const float* src = (const float*)d_in[1];
    const float* Wq  = (const float*)d_in[2];
    const float* Wk  = (const float*)d_in[3];
    const float* Wv  = (const float*)d_in[4];
    const float* Wm  = (const float*)d_in[5];
    const float* W1  = (const float*)d_in[6];
    const float* W2  = (const float*)d_in[7];
    const float* g1  = (const float*)d_in[8];
    const float* b1  = (const float*)d_in[9];
    const float* g2  = (const float*)d_in[10];
    const float* b2  = (const float*)d_in[11];
    const float* xm  = (const float*)d_in[12];
    const float* sm  = (const float*)d_in[13];
    float* out = (float*)d_out;

    float *Q,*Kf,*Vf,*KV,*Ks,*Zb,*msg,*msg2,*t,*h2;
    cudaGetSymbolAddress((void**)&Q,    g_Q);
    cudaGetSymbolAddress((void**)&Kf,   g_Kf);
    cudaGetSymbolAddress((void**)&Vf,   g_Vf);
    cudaGetSymbolAddress((void**)&KV,   g_KV);
    cudaGetSymbolAddress((void**)&Ks,   g_Ksum);
    cudaGetSymbolAddress((void**)&Zb,   g_Z);
    cudaGetSymbolAddress((void**)&msg,  g_msg);
    cudaGetSymbolAddress((void**)&msg2, g_msg2);
    cudaGetSymbolAddress((void**)&t,    g_t);
    cudaGetSymbolAddress((void**)&h2,   g_h2);

    dim3 blk(256);

    // projections (note: v/v_len and *v_len cancel exactly -> skipped)
    gemm_nt<EPI_ELU1><<<dim3(DM/128, ROWS/128), blk>>>(x,   Wq, Q,  ROWS, DM, DM, xm);
    gemm_nt<EPI_ELU1><<<dim3(DM/128, ROWS/128), blk>>>(src, Wk, Kf, ROWS, DM, DM, sm);
    gemm_nt<EPI_MASK><<<dim3(DM/128, ROWS/128), blk>>>(src, Wv, Vf, ROWS, DM, DM, sm);

    // linear attention
    ksum_kernel<<<(NB*DM)/256, 256>>>(Kf, Ks);
    gemm_tn_batch<<<dim3(DM/128, DM/128, NB), blk>>>(Kf, Vf, KV);
    z_kernel<<<(ROWS*32)/256, 256>>>(Q, Ks, Zb);
    gemm_nn_batch<<<dim3(DM/128, LL/128, NB), blk>>>(Q, KV, msg, Zb);

    // merge + MLP block
    gemm_nt<EPI_NONE><<<dim3(DM/128, ROWS/128), blk>>>(msg, Wm, msg2, ROWS, DM, DM, nullptr);
    ln_kernel<<<ROWS, 128>>>(msg2, g1, b1, msg2);
    gemm_cat_relu<<<dim3((2*DM)/128, ROWS/128), blk>>>(x, msg2, W1, t);
    gemm_nt<EPI_NONE><<<dim3(DM/128, ROWS/128), blk>>>(t, W2, h2, ROWS, DM, 2*DM, nullptr);
    ln_res_kernel<<<ROWS, 128>>>(h2, x, g2, b2, out);
}

// round 3
// speedup vs baseline: 1.3751x; 1.3751x over previous
#include <cuda_runtime.h>
#include <cuda_bf16.h>
#include <mma.h>
#include <math.h>
#include <stdint.h>

using namespace nvcuda;

// Problem constants (fixed by setup_inputs)
#define NB   64
#define LL   1024
#define DM   512
#define ROWS (NB*LL)          // 65536

// ---------------- scratch (static device globals; no allocation) ----------
__device__ float g_Q   [(size_t)ROWS*DM];
__device__ float g_KfT [(size_t)NB*DM*LL];   // [n][d][s]
__device__ float g_VfT [(size_t)NB*DM*LL];   // [n][v][s]
__device__ float g_KVT [(size_t)NB*DM*DM];   // [n][v][d]
__device__ float g_Ksum[NB*DM];
__device__ float g_Z   [ROWS];
__device__ float g_msg [(size_t)ROWS*DM];
__device__ float g_msg2[(size_t)ROWS*DM];
__device__ float g_t   [(size_t)ROWS*2*DM];
__device__ float g_h2  [(size_t)ROWS*DM];

enum { E_NONE=0, E_ELU1=1, E_MASK=2, E_Z=3, E_RELU=4 };

// smem geometry
#define BK    32
#define LDAB  40                   // bf16 elems per row (padded)
#define T_AH  0
#define T_AL  10240
#define T_BH  20480
#define T_BL  30720
#define BUF_BYTES 40960            // 4 tiles of 128x40 bf16
#define SMEM_BYTES 81920           // 2 buffers; epilogue stage reuses (67584B)
#define LDST  132                  // fp32 stage stride

// =====================================================================
// bf16 3-term split NT GEMM: C[M,N] = A[M,K] @ B[N,K]^T  (K-major)
// CTA tile 128x128, BK=32, 256 threads / 8 warps (warp tile 32x64)
// =====================================================================
template<int EPI, bool TRANSC, bool CAT>
__global__ void __launch_bounds__(256)
gemm_tc(const float* __restrict__ A1, const float* __restrict__ A2,
        const float* __restrict__ B,  float* __restrict__ C,
        const float* __restrict__ rs,
        int K, int M_batch, long long a_bs, long long b_bs, long long c_bs, int nld)
{
    extern __shared__ char smx[];
    const int tid  = threadIdx.x;
    const int wid  = tid >> 5;
    const int lane = tid & 31;
    const int wm   = wid & 3;          // warp row block (32 rows)
    const int wn   = wid >> 2;         // warp col block (64 cols)
    const int bm   = blockIdx.y * 128;
    const int bn   = blockIdx.x * 128;
    const int z    = blockIdx.z;
    const float* Ab = A1 + (size_t)z * a_bs;
    const float* Bb = B  + (size_t)z * b_bs;

    wmma::fragment<wmma::accumulator,16,16,16,float> acc[2][4];
#pragma unroll
    for (int i=0;i<2;i++)
#pragma unroll
        for (int j=0;j<4;j++) wmma::fill_fragment(acc[i][j], 0.f);

    float4 ra[4], rb[4];

    const int KT = K / BK;

    // ---- load chunk kt into registers ----
    auto LOAD = [&](int kt){
        const int k0 = kt * BK;
#pragma unroll
        for (int it=0; it<4; it++){
            int idx = tid + it*256;
            int r   = idx >> 3;
            int c4  = idx & 7;
            int kk  = k0 + c4*4;
            const float* ap;
            if (CAT) ap = (kk < DM) ? (A1 + (size_t)(bm+r)*DM + kk)
                                    : (A2 + (size_t)(bm+r)*DM + (kk-DM));
            else     ap = Ab + (size_t)(bm+r)*K + kk;
            ra[it] = *(const float4*)ap;
            rb[it] = *(const float4*)(Bb + (size_t)(bn+r)*K + kk);
        }
    };

    // ---- convert + store registers into smem buffer ----
    auto STORE = [&](int buf){
        char* base = smx + buf * BUF_BYTES;
#pragma unroll
        for (int it=0; it<4; it++){
            int idx = tid + it*256;
            int r   = idx >> 3;
            int c4  = idx & 7;
            int off = (r*LDAB + c4*4) * 2;   // bytes
            {
                float4 v = ra[it];
                __nv_bfloat16 hx=__float2bfloat16_rn(v.x), hy=__float2bfloat16_rn(v.y);
                __nv_bfloat16 hz=__float2bfloat16_rn(v.z), hw=__float2bfloat16_rn(v.w);
                __nv_bfloat16 lx=__float2bfloat16_rn(v.x-__bfloat162float(hx));
                __nv_bfloat16 ly=__float2bfloat16_rn(v.y-__bfloat162float(hy));
                __nv_bfloat16 lz=__float2bfloat16_rn(v.z-__bfloat162float(hz));
                __nv_bfloat16 lw=__float2bfloat16_rn(v.w-__bfloat162float(hw));
                __nv_bfloat162* dh = (__nv_bfloat162*)(base + T_AH + off);
                dh[0] = __nv_bfloat162(hx,hy); dh[1] = __nv_bfloat162(hz,hw);
                __nv_bfloat162* dl = (__nv_bfloat162*)(base + T_AL + off);
                dl[0] = __nv_bfloat162(lx,ly); dl[1] = __nv_bfloat162(lz,lw);
            }
            {
                float4 v = rb[it];
                __nv_bfloat16 hx=__float2bfloat16_rn(v.x), hy=__float2bfloat16_rn(v.y);
                __nv_bfloat16 hz=__float2bfloat16_rn(v.z), hw=__float2bfloat16_rn(v.w);
                __nv_bfloat16 lx=__float2bfloat16_rn(v.x-__bfloat162float(hx));
                __nv_bfloat16 ly=__float2bfloat16_rn(v.y-__bfloat162float(hy));
                __nv_bfloat16 lz=__float2bfloat16_rn(v.z-__bfloat162float(hz));
                __nv_bfloat16 lw=__float2bfloat16_rn(v.w-__bfloat162float(hw));
                __nv_bfloat162* dh = (__nv_bfloat162*)(base + T_BH + off);
                dh[0] = __nv_bfloat162(hx,hy); dh[1] = __nv_bfloat162(hz,hw);
                __nv_bfloat162* dl = (__nv_bfloat162*)(base + T_BL + off);
                dl[0] = __nv_bfloat162(lx,ly); dl[1] = __nv_bfloat162(lz,lw);
            }
        }
    };

    // ---- wmma compute on one buffer ----
    auto COMPUTE = [&](int buf){
        const __nv_bfloat16* Ah = (const __nv_bfloat16*)(smx + buf*BUF_BYTES + T_AH);
        const __nv_bfloat16* Al = (const __nv_bfloat16*)(smx + buf*BUF_BYTES + T_AL);
        const __nv_bfloat16* Bh = (const __nv_bfloat16*)(smx + buf*BUF_BYTES + T_BH);
        const __nv_bfloat16* Bl = (const __nv_bfloat16*)(smx + buf*BUF_BYTES + T_BL);
#pragma unroll
        for (int ks=0; ks<2; ks++){
            wmma::fragment<wmma::matrix_a,16,16,16,__nv_bfloat16,wmma::row_major> fah[2], fal[2];
#pragma unroll
            for (int i=0;i<2;i++){
                wmma::load_matrix_sync(fah[i], Ah + (wm*32+i*16)*LDAB + ks*16, LDAB);
                wmma::load_matrix_sync(fal[i], Al + (wm*32+i*16)*LDAB + ks*16, LDAB);
            }
#pragma unroll
            for (int j=0;j<4;j++){
                wmma::fragment<wmma::matrix_b,16,16,16,__nv_bfloat16,wmma::col_major> fbh, fbl;
                wmma::load_matrix_sync(fbh, Bh + (wn*64+j*16)*LDAB + ks*16, LDAB);
                wmma::load_matrix_sync(fbl, Bl + (wn*64+j*16)*LDAB + ks*16, LDAB);
#pragma unroll
                for (int i=0;i<2;i++){
                    wmma::mma_sync(acc[i][j], fah[i], fbh, acc[i][j]);
                    wmma::mma_sync(acc[i][j], fah[i], fbl, acc[i][j]);
                    wmma::mma_sync(acc[i][j], fal[i], fbh, acc[i][j]);
                }
            }
        }
    };

    LOAD(0);
    STORE(0);
    __syncthreads();
    for (int kt=0; kt<KT; kt++){
        if (kt+1 < KT) LOAD(kt+1);
        COMPUTE(kt & 1);
        __syncthreads();
        if (kt+1 < KT){ STORE((kt+1) & 1); __syncthreads(); }
    }

    // ---------------- epilogue via smem stage ----------------
    float* stage = (float*)smx;
#pragma unroll
    for (int i=0;i<2;i++)
#pragma unroll
        for (int j=0;j<4;j++){
            if (!TRANSC)
                wmma::store_matrix_sync(stage + (wm*32+i*16)*LDST + wn*64 + j*16,
                                        acc[i][j], LDST, wmma::mem_row_major);
            else
                wmma::store_matrix_sync(stage + (wn*64+j*16)*LDST + wm*32 + i*16,
                                        acc[i][j], LDST, wmma::mem_col_major);
        }
    __syncthreads();

    if (!TRANSC){
#pragma unroll
        for (int i=0;i<16;i++){
            int r  = wid*16 + i;
            int gm = bm + r;
            size_t grow = (size_t)z * M_batch + gm;
            float scale = 1.f;
            if (EPI==E_ELU1 || EPI==E_MASK || EPI==E_Z) scale = rs[grow];
            float4 v = *(const float4*)(stage + r*LDST + lane*4);
            float o[4] = {v.x, v.y, v.z, v.w};
#pragma unroll
            for (int c=0;c<4;c++){
                float x = o[c];
                if      (EPI==E_ELU1) x = (x > 0.f ? x + 1.f : expf(x)) * scale;
                else if (EPI==E_MASK) x = x * scale;
                else if (EPI==E_Z)    x = x * scale;
                else if (EPI==E_RELU) x = fmaxf(x, 0.f);
                o[c] = x;
            }
            float4 w = {o[0],o[1],o[2],o[3]};
            *(float4*)(C + (size_t)z*c_bs + (size_t)gm*nld + bn + lane*4) = w;
        }
    } else {
        // transposed per-batch store: CT[n][col][s]  (n from global row; z==0 here)
        const int s0 = bm & (LL-1);
        const int n  = bm >> 10;
#pragma unroll
        for (int i=0;i<16;i++){
            int c = wid*16 + i;
            float4 v = *(const float4*)(stage + c*LDST + lane*4);
            float o[4] = {v.x, v.y, v.z, v.w};
            if (EPI==E_ELU1 || EPI==E_MASK){
                float4 sc = *(const float4*)(rs + bm + lane*4);
                float s[4] = {sc.x, sc.y, sc.z, sc.w};
#pragma unroll
                for (int cte=0;cte<4;cte++){
                    float x = o[cte];
                    if (EPI==E_ELU1) x = (x > 0.f ? x + 1.f : expf(x)) * s[cte];
                    else             x = x * s[cte];
                    o[cte] = x;
                }
            }
            float4 w = {o[0],o[1],o[2],o[3]};
            *(float4*)(C + (size_t)n*DM*LL + (size_t)(bn + c)*LL + s0 + lane*4) = w;
        }
    }
}

// ---------------- Ksum from KfT: Ks[n*512+d] = sum_s KfT[n][d][s] ----------
__global__ void ksumT_kernel(const float* __restrict__ KfT, float* __restrict__ Ks)
{
    int wid = threadIdx.x >> 5, lane = threadIdx.x & 31;
    int row = blockIdx.x * 8 + wid;            // 0..NB*DM-1
    const float4* p = (const float4*)(KfT + (size_t)row * LL);
    float s = 0.f;
#pragma unroll
    for (int i = 0; i < 8; i++) { float4 v = p[lane + i*32]; s += v.x+v.y+v.z+v.w; }
#pragma unroll
    for (int o = 16; o; o >>= 1) s += __shfl_xor_sync(0xffffffffu, s, o);
    if (!lane) Ks[row] = s;
}

// ---------------- Z: Z[r] = 1/(dot(Q[r], Ksum[n]) + 1e-6) -----------------
__global__ void z_kernel(const float* __restrict__ Q,
                         const float* __restrict__ Ks,
                         float* __restrict__ Z)
{
    int gw   = (blockIdx.x*blockDim.x + threadIdx.x) >> 5;
    int lane = threadIdx.x & 31;
    if (gw >= ROWS) return;
    int n = gw >> 10;
    const float* q = Q  + (size_t)gw*DM;
    const float* k = Ks + n*DM;
    float s = 0.f;
#pragma unroll
    for (int i = 0; i < DM/32; i++) s = fmaf(q[lane + i*32], k[lane + i*32], s);
#pragma unroll
    for (int off = 16; off; off >>= 1) s += __shfl_xor_sync(0xffffffffu, s, off);
    if (lane == 0) Z[gw] = 1.f / (s + 1e-6f);
}

// ---------------- LayerNorm over rows of 512 ------------------------------
__global__ void ln_kernel(const float* __restrict__ in,
                          const float* __restrict__ g, const float* __restrict__ b,
                          float* __restrict__ out)
{
    int row = blockIdx.x;
    int tid = threadIdx.x;
    float4 v = *(const float4*)(in + (size_t)row*DM + tid*4);
    __shared__ float red[128];
    red[tid] = v.x + v.y + v.z + v.w;
    __syncthreads();
    for (int off = 64; off; off >>= 1) { if (tid < off) red[tid] += red[tid+off]; __syncthreads(); }
    float mu = red[0] * (1.f/DM);
    __syncthreads();
    float dx = v.x-mu, dy = v.y-mu, dz = v.z-mu, dw = v.w-mu;
    red[tid] = dx*dx + dy*dy + dz*dz + dw*dw;
    __syncthreads();
    for (int off = 64; off; off >>= 1) { if (tid < off) red[tid] += red[tid+off]; __syncthreads(); }
    float rstd = rsqrtf(red[0] * (1.f/DM) + 1e-5f);
    float4 gv = *(const float4*)(g + tid*4);
    float4 bv = *(const float4*)(b + tid*4);
    float4 o;
    o.x = dx*rstd*gv.x + bv.x; o.y = dy*rstd*gv.y + bv.y;
    o.z = dz*rstd*gv.z + bv.z; o.w = dw*rstd*gv.w + bv.w;
    *(float4*)(out + (size_t)row*DM + tid*4) = o;
}

__global__ void ln_res_kernel(const float* __restrict__ in,
                              const float* __restrict__ x,
                              const float* __restrict__ g, const float* __restrict__ b,
                              float* __restrict__ out)
{
    int row = blockIdx.x;
    int tid = threadIdx.x;
    float4 v = *(const float4*)(in + (size_t)row*DM + tid*4);
    __shared__ float red[128];
    red[tid] = v.x + v.y + v.z + v.w;
    __syncthreads();
    for (int off = 64; off; off >>= 1) { if (tid < off) red[tid] += red[tid+off]; __syncthreads(); }
    float mu = red[0] * (1.f/DM);
    __syncthreads();
    float dx = v.x-mu, dy = v.y-mu, dz = v.z-mu, dw = v.w-mu;
    red[tid] = dx*dx + dy*dy + dz*dz + dw*dw;
    __syncthreads();
    for (int off = 64; off; off >>= 1) { if (tid < off) red[tid] += red[tid+off]; __syncthreads(); }
    float rstd = rsqrtf(red[0] * (1.f/DM) + 1e-5f);
    float4 gv = *(const float4*)(g + tid*4);
    float4 bv = *(const float4*)(b + tid*4);
    float4 xv = *(const float4*)(x + (size_t)row*DM + tid*4);
    float4 o;
    o.x = xv.x + dx*rstd*gv.x + bv.x; o.y = xv.y + dy*rstd*gv.y + bv.y;
    o.z = xv.z + dz*rstd*gv.z + bv.z; o.w = xv.w + dw*rstd*gv.w + bv.w;
    *(float4*)(out + (size_t)row*DM + tid*4) = o;
}

// =====================================================================
extern "C" void kernel_launch(void* const* d_in, const int* in_sizes, int n_in,
                              void* d_out, int out_size)
{
    const float* x   = (const float*)d_in[0];
    const float* src = (const float*)d_in[1];
    const float* Wq  = (const float*)d_in[2];
    const float* Wk  = (const float*)d_in[3];
    const float* Wv  = (const float*)d_in[4];
    const float* Wm  = (const float*)d_in[5];
    const float* W1  = (const float*)d_in[6];
    const float* W2  = (const float*)d_in[7];
    const float* g1  = (const float*)d_in[8];
    const float* b1  = (const float*)d_in[9];
    const float* g2  = (const float*)d_in[10];
    const float* b2  = (const float*)d_in[11];
    const float* xm  = (const float*)d_in[12];
    const float* sm_ = (const float*)d_in[13];
    float* out = (float*)d_out;

    float *Q,*KfT,*VfT,*KVT,*Ks,*Zb,*msg,*msg2,*t,*h2;
    cudaGetSymbolAddress((void**)&Q,    g_Q);
    cudaGetSymbolAddress((void**)&KfT,  g_KfT);
    cudaGetSymbolAddress((void**)&VfT,  g_VfT);
    cudaGetSymbolAddress((void**)&KVT,  g_KVT);
    cudaGetSymbolAddress((void**)&Ks,   g_Ksum);
    cudaGetSymbolAddress((void**)&Zb,   g_Z);
    cudaGetSymbolAddress((void**)&msg,  g_msg);
    cudaGetSymbolAddress((void**)&msg2, g_msg2);
    cudaGetSymbolAddress((void**)&t,    g_t);
    cudaGetSymbolAddress((void**)&h2,   g_h2);

    // opt-in to 80KB dynamic smem for every instantiation
    cudaFuncSetAttribute((const void*)gemm_tc<E_ELU1,false,false>, cudaFuncAttributeMaxDynamicSharedMemorySize, SMEM_BYTES);
    cudaFuncSetAttribute((const void*)gemm_tc<E_ELU1,true ,false>, cudaFuncAttributeMaxDynamicSharedMemorySize, SMEM_BYTES);
    cudaFuncSetAttribute((const void*)gemm_tc<E_MASK,true ,false>, cudaFuncAttributeMaxDynamicSharedMemorySize, SMEM_BYTES);
    cudaFuncSetAttribute((const void*)gemm_tc<E_NONE,false,false>, cudaFuncAttributeMaxDynamicSharedMemorySize, SMEM_BYTES);
    cudaFuncSetAttribute((const void*)gemm_tc<E_Z   ,false,false>, cudaFuncAttributeMaxDynamicSharedMemorySize, SMEM_BYTES);
    cudaFuncSetAttribute((const void*)gemm_tc<E_RELU,false,true >, cudaFuncAttributeMaxDynamicSharedMemorySize, SMEM_BYTES);

    dim3 blk(256);

    // 1) Q = (elu(x@Wq^T)+1) * x_mask                   [65536,512]
    gemm_tc<E_ELU1,false,false><<<dim3(4,512,1), blk, SMEM_BYTES>>>(
        x, nullptr, Wq, Q, xm, DM, ROWS, 0, 0, 0, DM);
    // 2) KfT = ((elu(src@Wk^T)+1)*src_mask)^T per batch [64][512][1024]
    gemm_tc<E_ELU1,true ,false><<<dim3(4,512,1), blk, SMEM_BYTES>>>(
        src, nullptr, Wk, KfT, sm_, DM, ROWS, 0, 0, 0, DM);
    // 3) VfT = ((src@Wv^T)*src_mask)^T per batch        [64][512][1024]
    gemm_tc<E_MASK,true ,false><<<dim3(4,512,1), blk, SMEM_BYTES>>>(
        src, nullptr, Wv, VfT, sm_, DM, ROWS, 0, 0, 0, DM);

    // 4) Ksum, 5) Z
    ksumT_kernel<<<(NB*DM)/8, 256>>>(KfT, Ks);
    z_kernel<<<(ROWS*32)/256, 256>>>(Q, Ks, Zb);

    // 6) KVT[n] = VfT[n] @ KfT[n]^T  (K=1024)           [64][512][512]
    gemm_tc<E_NONE,false,false><<<dim3(4,4,NB), blk, SMEM_BYTES>>>(
        VfT, nullptr, KfT, KVT, nullptr, LL, DM,
        (long long)DM*LL, (long long)DM*LL, (long long)DM*DM, DM);
    // 7) msg[n] = (Q[n] @ KVT[n]^T) * Z                 [64][1024][512]
    gemm_tc<E_Z,false,false><<<dim3(4,8,NB), blk, SMEM_BYTES>>>(
        Q, nullptr, KVT, msg, Zb, DM, LL,
        (long long)LL*DM, (long long)DM*DM, (long long)LL*DM, DM);

    // 8) msg2 = msg @ Wm^T                               [65536,512]
    gemm_tc<E_NONE,false,false><<<dim3(4,512,1), blk, SMEM_BYTES>>>(
        msg, nullptr, Wm, msg2, nullptr, DM, ROWS, 0, 0, 0, DM);
    // 9) LN1 in place
    ln_kernel<<<ROWS, 128>>>(msg2, g1, b1, msg2);
    // 10) t = relu([x|msg2] @ W1^T)                      [65536,1024]
    gemm_tc<E_RELU,false,true ><<<dim3(8,512,1), blk, SMEM_BYTES>>>(
        x, msg2, W1, t, nullptr, 2*DM, ROWS, 0, 0, 0, 2*DM);
    // 11) h2 = t @ W2^T                                  [65536,512]
    gemm_tc<E_NONE,false,false><<<dim3(4,512,1), blk, SMEM_BYTES>>>(
        t, nullptr, W2, h2, nullptr, 2*DM, ROWS, 0, 0, 0, DM);
    // 12) out = x + LN2(h2)
    ln_res_kernel<<<ROWS, 128>>>(h2, x, g2, b2, out);
}

// round 4
// speedup vs baseline: 1.6720x; 1.2159x over previous
#include <cuda_runtime.h>
#include <cuda_bf16.h>
#include <mma.h>
#include <math.h>
#include <stdint.h>

using namespace nvcuda;

#define NB   64
#define LL   1024
#define DM   512
#define ROWS (NB*LL)          // 65536

// ---------------- persistent bf16 hi/lo planes + fp32 scratch -------------
__device__ __nv_bfloat16 g_xh [(size_t)ROWS*DM],  g_xl [(size_t)ROWS*DM];
__device__ __nv_bfloat16 g_sh [(size_t)ROWS*DM],  g_sl [(size_t)ROWS*DM];
__device__ __nv_bfloat16 g_Wqh[DM*DM], g_Wql[DM*DM];
__device__ __nv_bfloat16 g_Wkh[DM*DM], g_Wkl[DM*DM];
__device__ __nv_bfloat16 g_Wvh[DM*DM], g_Wvl[DM*DM];
__device__ __nv_bfloat16 g_Wmh[DM*DM], g_Wml[DM*DM];
__device__ __nv_bfloat16 g_W1h[4*DM*DM], g_W1l[4*DM*DM];
__device__ __nv_bfloat16 g_W2h[2*DM*DM], g_W2l[2*DM*DM];
__device__ __nv_bfloat16 g_Qh  [(size_t)ROWS*DM], g_Ql  [(size_t)ROWS*DM];
__device__ __nv_bfloat16 g_KfTh[(size_t)ROWS*DM], g_KfTl[(size_t)ROWS*DM];
__device__ __nv_bfloat16 g_VfTh[(size_t)ROWS*DM], g_VfTl[(size_t)ROWS*DM];
__device__ __nv_bfloat16 g_KVTh[(size_t)NB*DM*DM], g_KVTl[(size_t)NB*DM*DM];
__device__ __nv_bfloat16 g_msgh[(size_t)ROWS*DM], g_msgl[(size_t)ROWS*DM];
__device__ __nv_bfloat16 g_m2h [(size_t)ROWS*DM], g_m2l [(size_t)ROWS*DM];
__device__ __nv_bfloat16 g_th  [(size_t)ROWS*2*DM], g_tl [(size_t)ROWS*2*DM];
__device__ float g_msg2f[(size_t)ROWS*DM];
__device__ float g_h2f  [(size_t)ROWS*DM];
__device__ float g_Ksum [NB*DM];
__device__ float g_Z    [ROWS];

enum { E_NONE=0, E_ELU1=1, E_MASK=2, E_Z=3, E_RELU=4 };

// smem geometry: 4 stages, each = 4 tiles (AH,AL,BH,BL) of 128x(32+8pad) bf16
#define BK    32
#define LDAB  40
#define TILE_BYTES 10240
#define BUF_BYTES  40960
#define SMEM_BYTES 163840
#define LDST  132

__device__ __forceinline__ void cpa16(uint32_t dst, const void* src){
    asm volatile("cp.async.cg.shared.global [%0], [%1], 16;" :: "r"(dst), "l"(src) : "memory");
}
#define CP_COMMIT() asm volatile("cp.async.commit_group;" ::: "memory")

__device__ __forceinline__ void hilo(float x, __nv_bfloat16& h, __nv_bfloat16& l){
    h = __float2bfloat16_rn(x);
    l = __float2bfloat16_rn(x - __bfloat162float(h));
}

// =====================================================================
// bf16 3-term split NT GEMM (cp.async 4-stage): C = A @ B^T, K-major
// CTA 128x128, BK=32, 256 thr / 8 warps (warp tile 32x64)
// =====================================================================
template<int EPI, bool TRANSC, bool CAT, bool OBF, bool OF32>
__global__ void __launch_bounds__(256)
gemm_tc(const __nv_bfloat16* __restrict__ A1h, const __nv_bfloat16* __restrict__ A1l,
        const __nv_bfloat16* __restrict__ A2h, const __nv_bfloat16* __restrict__ A2l,
        const __nv_bfloat16* __restrict__ Bh,  const __nv_bfloat16* __restrict__ Bl,
        __nv_bfloat16* __restrict__ Ch, __nv_bfloat16* __restrict__ Cl,
        float* __restrict__ Cf, const float* __restrict__ rs,
        int K, int M_batch, long long a_bs, long long b_bs, long long c_bs, int nld)
{
    extern __shared__ char smx[];
    const uint32_t sb = (uint32_t)__cvta_generic_to_shared(smx);
    const int tid  = threadIdx.x;
    const int wid  = tid >> 5;
    const int lane = tid & 31;
    const int wm   = wid & 3;
    const int wn   = wid >> 2;
    const int bm   = blockIdx.y * 128;
    const int bn   = blockIdx.x * 128;
    const int z    = blockIdx.z;
    const __nv_bfloat16* Abh = A1h + (size_t)z * a_bs;
    const __nv_bfloat16* Abl = A1l + (size_t)z * a_bs;
    const __nv_bfloat16* Bbh = Bh  + (size_t)z * b_bs;
    const __nv_bfloat16* Bbl = Bl  + (size_t)z * b_bs;

    wmma::fragment<wmma::accumulator,16,16,16,float> acc[2][4];
#pragma unroll
    for (int i=0;i<2;i++)
#pragma unroll
        for (int j=0;j<4;j++) wmma::fill_fragment(acc[i][j], 0.f);

    const int KT = K / BK;

    auto ISSUE = [&](int kt, int buf){
        const int k0 = kt * BK;
        const uint32_t base = sb + buf * BUF_BYTES;
#pragma unroll
        for (int i=0;i<8;i++){
            int idx = tid + i*256;
            int r   = (idx >> 2) & 127;
            int c   = idx & 3;
            int kk  = k0 + c*8;
            uint32_t dst = base + (i>>1)*TILE_BYTES + r*80 + c*16;
            const __nv_bfloat16* src;
            switch (i>>1){
              case 0: src = CAT ? ((kk<DM) ? A1h + (size_t)(bm+r)*DM + kk
                                           : A2h + (size_t)(bm+r)*DM + (kk-DM))
                                : Abh + (size_t)(bm+r)*K + kk; break;
              case 1: src = CAT ? ((kk<DM) ? A1l + (size_t)(bm+r)*DM + kk
                                           : A2l + (size_t)(bm+r)*DM + (kk-DM))
                                : Abl + (size_t)(bm+r)*K + kk; break;
              case 2: src = Bbh + (size_t)(bn+r)*K + kk; break;
              default:src = Bbl + (size_t)(bn+r)*K + kk; break;
            }
            cpa16(dst, src);
        }
    };

    auto COMPUTE = [&](int buf){
        const __nv_bfloat16* Ah_ = (const __nv_bfloat16*)(smx + buf*BUF_BYTES);
        const __nv_bfloat16* Al_ = (const __nv_bfloat16*)(smx + buf*BUF_BYTES + TILE_BYTES);
        const __nv_bfloat16* Bh_ = (const __nv_bfloat16*)(smx + buf*BUF_BYTES + 2*TILE_BYTES);
        const __nv_bfloat16* Bl_ = (const __nv_bfloat16*)(smx + buf*BUF_BYTES + 3*TILE_BYTES);
#pragma unroll
        for (int ks=0; ks<2; ks++){
            wmma::fragment<wmma::matrix_a,16,16,16,__nv_bfloat16,wmma::row_major> fah[2], fal[2];
#pragma unroll
            for (int i=0;i<2;i++){
                wmma::load_matrix_sync(fah[i], Ah_ + (wm*32+i*16)*LDAB + ks*16, LDAB);
                wmma::load_matrix_sync(fal[i], Al_ + (wm*32+i*16)*LDAB + ks*16, LDAB);
            }
#pragma unroll
            for (int j=0;j<4;j++){
                wmma::fragment<wmma::matrix_b,16,16,16,__nv_bfloat16,wmma::col_major> fbh, fbl;
                wmma::load_matrix_sync(fbh, Bh_ + (wn*64+j*16)*LDAB + ks*16, LDAB);
                wmma::load_matrix_sync(fbl, Bl_ + (wn*64+j*16)*LDAB + ks*16, LDAB);
#pragma unroll
                for (int i=0;i<2;i++){
                    wmma::mma_sync(acc[i][j], fah[i], fbh, acc[i][j]);
                    wmma::mma_sync(acc[i][j], fah[i], fbl, acc[i][j]);
                    wmma::mma_sync(acc[i][j], fal[i], fbh, acc[i][j]);
                }
            }
        }
    };

    ISSUE(0,0); CP_COMMIT();
    ISSUE(1,1); CP_COMMIT();
    ISSUE(2,2); CP_COMMIT();

    for (int kt=0; kt<KT; kt++){
        if (kt < KT-2)       asm volatile("cp.async.wait_group 2;" ::: "memory");
        else if (kt == KT-2) asm volatile("cp.async.wait_group 1;" ::: "memory");
        else                 asm volatile("cp.async.wait_group 0;" ::: "memory");
        __syncthreads();
        if (kt+3 < KT){ ISSUE(kt+3, (kt+3)&3); CP_COMMIT(); }
        COMPUTE(kt & 3);
    }

    // ---------------- epilogue via smem stage ----------------
    __syncthreads();
    float* stage = (float*)smx;
#pragma unroll
    for (int i=0;i<2;i++)
#pragma unroll
        for (int j=0;j<4;j++){
            if (!TRANSC)
                wmma::store_matrix_sync(stage + (wm*32+i*16)*LDST + wn*64 + j*16,
                                        acc[i][j], LDST, wmma::mem_row_major);
            else
                wmma::store_matrix_sync(stage + (wn*64+j*16)*LDST + wm*32 + i*16,
                                        acc[i][j], LDST, wmma::mem_col_major);
        }
    __syncthreads();

    if (!TRANSC){
#pragma unroll
        for (int i=0;i<16;i++){
            int r  = wid*16 + i;
            int gm = bm + r;
            size_t grow = (size_t)z * M_batch + gm;
            float scale = 1.f;
            if (EPI==E_ELU1 || EPI==E_MASK || EPI==E_Z) scale = rs[grow];
            float4 v = *(const float4*)(stage + r*LDST + lane*4);
            float o[4] = {v.x, v.y, v.z, v.w};
#pragma unroll
            for (int c=0;c<4;c++){
                float xx = o[c];
                if      (EPI==E_ELU1) xx = (xx > 0.f ? xx + 1.f : expf(xx)) * scale;
                else if (EPI==E_MASK) xx = xx * scale;
                else if (EPI==E_Z)    xx = xx * scale;
                else if (EPI==E_RELU) xx = fmaxf(xx, 0.f);
                o[c] = xx;
            }
            size_t coff = (size_t)z*c_bs + (size_t)gm*nld + bn + lane*4;
            if (OF32){
                float4 w = {o[0],o[1],o[2],o[3]};
                *(float4*)(Cf + coff) = w;
            }
            if (OBF){
                __nv_bfloat16 h[4], l[4];
#pragma unroll
                for (int c=0;c<4;c++) hilo(o[c], h[c], l[c]);
                *(__nv_bfloat162*)(Ch + coff)     = __nv_bfloat162(h[0],h[1]);
                *(__nv_bfloat162*)(Ch + coff + 2) = __nv_bfloat162(h[2],h[3]);
                *(__nv_bfloat162*)(Cl + coff)     = __nv_bfloat162(l[0],l[1]);
                *(__nv_bfloat162*)(Cl + coff + 2) = __nv_bfloat162(l[2],l[3]);
            }
        }
    } else {
        const int s0 = bm & (LL-1);
        const int n  = bm >> 10;
#pragma unroll
        for (int i=0;i<16;i++){
            int c = wid*16 + i;
            float4 v = *(const float4*)(stage + c*LDST + lane*4);
            float o[4] = {v.x, v.y, v.z, v.w};
            if (EPI==E_ELU1 || EPI==E_MASK){
                float4 sc = *(const float4*)(rs + bm + lane*4);
                float s[4] = {sc.x, sc.y, sc.z, sc.w};
#pragma unroll
                for (int ct=0;ct<4;ct++){
                    float xx = o[ct];
                    if (EPI==E_ELU1) xx = (xx > 0.f ? xx + 1.f : expf(xx)) * s[ct];
                    else             xx = xx * s[ct];
                    o[ct] = xx;
                }
            }
            size_t coff = (size_t)n*DM*LL + (size_t)(bn + c)*LL + s0 + lane*4;
            __nv_bfloat16 h[4], l[4];
#pragma unroll
            for (int ct=0;ct<4;ct++) hilo(o[ct], h[ct], l[ct]);
            *(__nv_bfloat162*)(Ch + coff)     = __nv_bfloat162(h[0],h[1]);
            *(__nv_bfloat162*)(Ch + coff + 2) = __nv_bfloat162(h[2],h[3]);
            *(__nv_bfloat162*)(Cl + coff)     = __nv_bfloat162(l[0],l[1]);
            *(__nv_bfloat162*)(Cl + coff + 2) = __nv_bfloat162(l[2],l[3]);
        }
    }
}

// ---------------- fp32 -> bf16 hi/lo converter ----------------------------
__global__ void cvt_hilo(const float* __restrict__ in,
                         __nv_bfloat16* __restrict__ hi,
                         __nv_bfloat16* __restrict__ lo, int n4)
{
    int i = blockIdx.x*blockDim.x + threadIdx.x;
    if (i >= n4) return;
    float4 v = ((const float4*)in)[i];
    __nv_bfloat16 h[4], l[4];
    hilo(v.x,h[0],l[0]); hilo(v.y,h[1],l[1]); hilo(v.z,h[2],l[2]); hilo(v.w,h[3],l[3]);
    ((__nv_bfloat162*)hi)[2*i]   = __nv_bfloat162(h[0],h[1]);
    ((__nv_bfloat162*)hi)[2*i+1] = __nv_bfloat162(h[2],h[3]);
    ((__nv_bfloat162*)lo)[2*i]   = __nv_bfloat162(l[0],l[1]);
    ((__nv_bfloat162*)lo)[2*i+1] = __nv_bfloat162(l[2],l[3]);
}

// ---------------- Ksum: Ks[n*512+d] = sum_s KfT[n][d][s] ------------------
__global__ void ksumT_kernel(const __nv_bfloat16* __restrict__ h,
                             const __nv_bfloat16* __restrict__ l,
                             float* __restrict__ Ks)
{
    int wid = threadIdx.x >> 5, lane = threadIdx.x & 31;
    int row = blockIdx.x * 8 + wid;
    const __nv_bfloat162* ph = (const __nv_bfloat162*)(h + (size_t)row * LL);
    const __nv_bfloat162* pl = (const __nv_bfloat162*)(l + (size_t)row * LL);
    float s = 0.f;
#pragma unroll
    for (int i = 0; i < 16; i++){
        __nv_bfloat162 a = ph[lane + i*32], b = pl[lane + i*32];
        s += __bfloat162float(a.x)+__bfloat162float(a.y)
           + __bfloat162float(b.x)+__bfloat162float(b.y);
    }
#pragma unroll
    for (int o = 16; o; o >>= 1) s += __shfl_xor_sync(0xffffffffu, s, o);
    if (!lane) Ks[row] = s;
}

// ---------------- Z: Z[r] = 1/(dot(Q[r], Ksum[n]) + 1e-6) -----------------
__global__ void z_kernel(const __nv_bfloat16* __restrict__ Qh,
                         const __nv_bfloat16* __restrict__ Ql,
                         const float* __restrict__ Ks, float* __restrict__ Z)
{
    int gw   = (blockIdx.x*blockDim.x + threadIdx.x) >> 5;
    int lane = threadIdx.x & 31;
    if (gw >= ROWS) return;
    int n = gw >> 10;
    const __nv_bfloat16* qh = Qh + (size_t)gw*DM;
    const __nv_bfloat16* ql = Ql + (size_t)gw*DM;
    const float* k = Ks + n*DM;
    float s = 0.f;
#pragma unroll
    for (int i = 0; i < DM/32; i++){
        int d = lane + i*32;
        float q = __bfloat162float(qh[d]) + __bfloat162float(ql[d]);
        s = fmaf(q, k[d], s);
    }
#pragma unroll
    for (int off = 16; off; off >>= 1) s += __shfl_xor_sync(0xffffffffu, s, off);
    if (lane == 0) Z[gw] = 1.f / (s + 1e-6f);
}

// ---------------- LayerNorm (fp32 in) -> bf16 hi/lo out -------------------
__global__ void ln_kernel_bf(const float* __restrict__ in,
                             const float* __restrict__ g, const float* __restrict__ b,
                             __nv_bfloat16* __restrict__ oh, __nv_bfloat16* __restrict__ ol)
{
    int row = blockIdx.x;
    int tid = threadIdx.x;
    float4 v = *(const float4*)(in + (size_t)row*DM + tid*4);
    __shared__ float red[128];
    red[tid] = v.x + v.y + v.z + v.w;
    __syncthreads();
    for (int off = 64; off; off >>= 1) { if (tid < off) red[tid] += red[tid+off]; __syncthreads(); }
    float mu = red[0] * (1.f/DM);
    __syncthreads();
    float dx = v.x-mu, dy = v.y-mu, dz = v.z-mu, dw = v.w-mu;
    red[tid] = dx*dx + dy*dy + dz*dz + dw*dw;
    __syncthreads();
    for (int off = 64; off; off >>= 1) { if (tid < off) red[tid] += red[tid+off]; __syncthreads(); }
    float rstd = rsqrtf(red[0] * (1.f/DM) + 1e-5f);
    float4 gv = *(const float4*)(g + tid*4);
    float4 bv = *(const float4*)(b + tid*4);
    float o0 = dx*rstd*gv.x + bv.x, o1 = dy*rstd*gv.y + bv.y;
    float o2 = dz*rstd*gv.z + bv.z, o3 = dw*rstd*gv.w + bv.w;
    __nv_bfloat16 h[4], l[4];
    hilo(o0,h[0],l[0]); hilo(o1,h[1],l[1]); hilo(o2,h[2],l[2]); hilo(o3,h[3],l[3]);
    size_t off4 = (size_t)row*DM + tid*4;
    *(__nv_bfloat162*)(oh + off4)     = __nv_bfloat162(h[0],h[1]);
    *(__nv_bfloat162*)(oh + off4 + 2) = __nv_bfloat162(h[2],h[3]);
    *(__nv_bfloat162*)(ol + off4)     = __nv_bfloat162(l[0],l[1]);
    *(__nv_bfloat162*)(ol + off4 + 2) = __nv_bfloat162(l[2],l[3]);
}

// ---------------- out = x + LN(h2) (all fp32) ------------------------------
__global__ void ln_res_kernel(const float* __restrict__ in,
                              const float* __restrict__ x,
                              const float* __restrict__ g, const float* __restrict__ b,
                              float* __restrict__ out)
{
    int row = blockIdx.x;
    int tid = threadIdx.x;
    float4 v = *(const float4*)(in + (size_t)row*DM + tid*4);
    __shared__ float red[128];
    red[tid] = v.x + v.y + v.z + v.w;
    __syncthreads();
    for (int off = 64; off; off >>= 1) { if (tid < off) red[tid] += red[tid+off]; __syncthreads(); }
    float mu = red[0] * (1.f/DM);
    __syncthreads();
    float dx = v.x-mu, dy = v.y-mu, dz = v.z-mu, dw = v.w-mu;
    red[tid] = dx*dx + dy*dy + dz*dz + dw*dw;
    __syncthreads();
    for (int off = 64; off; off >>= 1) { if (tid < off) red[tid] += red[tid+off]; __syncthreads(); }
    float rstd = rsqrtf(red[0] * (1.f/DM) + 1e-5f);
    float4 gv = *(const float4*)(g + tid*4);
    float4 bv = *(const float4*)(b + tid*4);
    float4 xv = *(const float4*)(x + (size_t)row*DM + tid*4);
    float4 o;
    o.x = xv.x + dx*rstd*gv.x + bv.x; o.y = xv.y + dy*rstd*gv.y + bv.y;
    o.z = xv.z + dz*rstd*gv.z + bv.z; o.w = xv.w + dw*rstd*gv.w + bv.w;
    *(float4*)(out + (size_t)row*DM + tid*4) = o;
}

// =====================================================================
extern "C" void kernel_launch(void* const* d_in, const int* in_sizes, int n_in,
                              void* d_out, int out_size)
{
    const float* x   = (const float*)d_in[0];
    const float* src = (const float*)d_in[1];
    const float* Wq  = (const float*)d_in[2];
    const float* Wk  = (const float*)d_in[3];
    const float* Wv  = (const float*)d_in[4];
    const float* Wm  = (const float*)d_in[5];
    const float* W1  = (const float*)d_in[6];
    const float* W2  = (const float*)d_in[7];
    const float* g1  = (const float*)d_in[8];
    const float* b1  = (const float*)d_in[9];
    const float* g2  = (const float*)d_in[10];
    const float* b2  = (const float*)d_in[11];
    const float* xm  = (const float*)d_in[12];
    const float* sm_ = (const float*)d_in[13];
    float* out = (float*)d_out;

    __nv_bfloat16 *xh,*xl,*sh,*sl,*Wqh,*Wql,*Wkh,*Wkl,*Wvh,*Wvl,*Wmh,*Wml,*W1h,*W1l,*W2h,*W2l;
    __nv_bfloat16 *Qh,*Ql,*KfTh,*KfTl,*VfTh,*VfTl,*KVTh,*KVTl,*msgh,*msgl,*m2h,*m2l,*th,*tl;
    float *msg2f,*h2f,*Ks,*Zb;
    cudaGetSymbolAddress((void**)&xh, g_xh);   cudaGetSymbolAddress((void**)&xl, g_xl);
    cudaGetSymbolAddress((void**)&sh, g_sh);   cudaGetSymbolAddress((void**)&sl, g_sl);
    cudaGetSymbolAddress((void**)&Wqh,g_Wqh);  cudaGetSymbolAddress((void**)&Wql,g_Wql);
    cudaGetSymbolAddress((void**)&Wkh,g_Wkh);  cudaGetSymbolAddress((void**)&Wkl,g_Wkl);
    cudaGetSymbolAddress((void**)&Wvh,g_Wvh);  cudaGetSymbolAddress((void**)&Wvl,g_Wvl);
    cudaGetSymbolAddress((void**)&Wmh,g_Wmh);  cudaGetSymbolAddress((void**)&Wml,g_Wml);
    cudaGetSymbolAddress((void**)&W1h,g_W1h);  cudaGetSymbolAddress((void**)&W1l,g_W1l);
    cudaGetSymbolAddress((void**)&W2h,g_W2h);  cudaGetSymbolAddress((void**)&W2l,g_W2l);
    cudaGetSymbolAddress((void**)&Qh, g_Qh);   cudaGetSymbolAddress((void**)&Ql, g_Ql);
    cudaGetSymbolAddress((void**)&KfTh,g_KfTh);cudaGetSymbolAddress((void**)&KfTl,g_KfTl);
    cudaGetSymbolAddress((void**)&VfTh,g_VfTh);cudaGetSymbolAddress((void**)&VfTl,g_VfTl);
    cudaGetSymbolAddress((void**)&KVTh,g_KVTh);cudaGetSymbolAddress((void**)&KVTl,g_KVTl);
    cudaGetSymbolAddress((void**)&msgh,g_msgh);cudaGetSymbolAddress((void**)&msgl,g_msgl);
    cudaGetSymbolAddress((void**)&m2h, g_m2h); cudaGetSymbolAddress((void**)&m2l, g_m2l);
    cudaGetSymbolAddress((void**)&th,  g_th);  cudaGetSymbolAddress((void**)&tl,  g_tl);
    cudaGetSymbolAddress((void**)&msg2f,g_msg2f);
    cudaGetSymbolAddress((void**)&h2f, g_h2f);
    cudaGetSymbolAddress((void**)&Ks,  g_Ksum);
    cudaGetSymbolAddress((void**)&Zb,  g_Z);

    cudaFuncSetAttribute((const void*)gemm_tc<E_ELU1,false,false,true ,false>, cudaFuncAttributeMaxDynamicSharedMemorySize, SMEM_BYTES);
    cudaFuncSetAttribute((const void*)gemm_tc<E_ELU1,true ,false,true ,false>, cudaFuncAttributeMaxDynamicSharedMemorySize, SMEM_BYTES);
    cudaFuncSetAttribute((const void*)gemm_tc<E_MASK,true ,false,true ,false>, cudaFuncAttributeMaxDynamicSharedMemorySize, SMEM_BYTES);
    cudaFuncSetAttribute((const void*)gemm_tc<E_NONE,false,false,true ,false>, cudaFuncAttributeMaxDynamicSharedMemorySize, SMEM_BYTES);
    cudaFuncSetAttribute((const void*)gemm_tc<E_Z   ,false,false,true ,false>, cudaFuncAttributeMaxDynamicSharedMemorySize, SMEM_BYTES);
    cudaFuncSetAttribute((const void*)gemm_tc<E_NONE,false,false,false,true >, cudaFuncAttributeMaxDynamicSharedMemorySize, SMEM_BYTES);
    cudaFuncSetAttribute((const void*)gemm_tc<E_RELU,false,true ,true ,false>, cudaFuncAttributeMaxDynamicSharedMemorySize, SMEM_BYTES);

    // ---- preconvert inputs & weights to bf16 hi/lo ----
    cvt_hilo<<<(ROWS*DM/4+255)/256,256>>>(x,   xh,  xl,  ROWS*DM/4);
    cvt_hilo<<<(ROWS*DM/4+255)/256,256>>>(src, sh,  sl,  ROWS*DM/4);
    cvt_hilo<<<(DM*DM/4+255)/256,  256>>>(Wq,  Wqh, Wql, DM*DM/4);
    cvt_hilo<<<(DM*DM/4+255)/256,  256>>>(Wk,  Wkh, Wkl, DM*DM/4);
    cvt_hilo<<<(DM*DM/4+255)/256,  256>>>(Wv,  Wvh, Wvl, DM*DM/4);
    cvt_hilo<<<(DM*DM/4+255)/256,  256>>>(Wm,  Wmh, Wml, DM*DM/4);
    cvt_hilo<<<(4*DM*DM/4+255)/256,256>>>(W1,  W1h, W1l, 4*DM*DM/4);
    cvt_hilo<<<(2*DM*DM/4+255)/256,256>>>(W2,  W2h, W2l, 2*DM*DM/4);

    dim3 blk(256);

    // 1) Q = (elu(x@Wq^T)+1) * x_mask            -> hi/lo [65536,512]
    gemm_tc<E_ELU1,false,false,true,false><<<dim3(4,512,1), blk, SMEM_BYTES>>>(
        xh, xl, nullptr, nullptr, Wqh, Wql, Qh, Ql, nullptr, xm,
        DM, ROWS, 0, 0, 0, DM);
    // 2) KfT = ((elu(src@Wk^T)+1)*mask)^T        -> hi/lo [64][512][1024]
    gemm_tc<E_ELU1,true,false,true,false><<<dim3(4,512,1), blk, SMEM_BYTES>>>(
        sh, sl, nullptr, nullptr, Wkh, Wkl, KfTh, KfTl, nullptr, sm_,
        DM, ROWS, 0, 0, 0, DM);
    // 3) VfT = ((src@Wv^T)*mask)^T               -> hi/lo [64][512][1024]
    gemm_tc<E_MASK,true,false,true,false><<<dim3(4,512,1), blk, SMEM_BYTES>>>(
        sh, sl, nullptr, nullptr, Wvh, Wvl, VfTh, VfTl, nullptr, sm_,
        DM, ROWS, 0, 0, 0, DM);

    // 4) Ksum, 5) Z
    ksumT_kernel<<<(NB*DM)/8, 256>>>(KfTh, KfTl, Ks);
    z_kernel<<<(ROWS*32)/256, 256>>>(Qh, Ql, Ks, Zb);

    // 6) KVT[n] = VfT[n] @ KfT[n]^T (K=1024)     -> hi/lo [64][512][512]
    gemm_tc<E_NONE,false,false,true,false><<<dim3(4,4,NB), blk, SMEM_BYTES>>>(
        VfTh, VfTl, nullptr, nullptr, KfTh, KfTl, KVTh, KVTl, nullptr, nullptr,
        LL, DM, (long long)DM*LL, (long long)DM*LL, (long long)DM*DM, DM);
    // 7) msg[n] = (Q[n] @ KVT[n]^T) * Z          -> hi/lo [64][1024][512]
    gemm_tc<E_Z,false,false,true,false><<<dim3(4,8,NB), blk, SMEM_BYTES>>>(
        Qh, Ql, nullptr, nullptr, KVTh, KVTl, msgh, msgl, nullptr, Zb,
        DM, LL, (long long)LL*DM, (long long)DM*DM, (long long)LL*DM, DM);

    // 8) msg2 = msg @ Wm^T                        -> fp32 [65536,512]
    gemm_tc<E_NONE,false,false,false,true><<<dim3(4,512,1), blk, SMEM_BYTES>>>(
        msgh, msgl, nullptr, nullptr, Wmh, Wml, nullptr, nullptr, msg2f, nullptr,
        DM, ROWS, 0, 0, 0, DM);
    // 9) LN1 -> bf16 hi/lo
    ln_kernel_bf<<<ROWS, 128>>>(msg2f, g1, b1, m2h, m2l);
    // 10) t = relu([x|msg2] @ W1^T)               -> hi/lo [65536,1024]
    gemm_tc<E_RELU,false,true,true,false><<<dim3(8,512,1), blk, SMEM_BYTES>>>(
        xh, xl, m2h, m2l, W1h, W1l, th, tl, nullptr, nullptr,
        2*DM, ROWS, 0, 0, 0, 2*DM);
    // 11) h2 = t @ W2^T                           -> fp32 [65536,512]
    gemm_tc<E_NONE,false,false,false,true><<<dim3(4,512,1), blk, SMEM_BYTES>>>(
        th, tl, nullptr, nullptr, W2h, W2l, nullptr, nullptr, h2f, nullptr,
        2*DM, ROWS, 0, 0, 0, DM);
    // 12) out = x + LN2(h2)
    ln_res_kernel<<<ROWS, 128>>>(h2f, x, g2, b2, out);
}